// round 5
// baseline (speedup 1.0000x reference)
#include <cuda_runtime.h>
#include <cstdint>

// WeightOnlyInt8Linear on GB300 — int8 IMMA (mma.sync.m16n8k32.s8) double-quant.
// out[M,N] = x[M,K] @ W[N,K]^T * scales[N] + bias[N],  M=2048, N=4096, K=4096.
//
// x = step1[m]*q1 + step2[m]*q2 (two int8 planes, step2=step1/256, rel err ~4e-5).
// W int32 -> int8 exact repack. Two s32-accumulated IMMA passes sharing B frags.
// CTA 128x128, k-chunk 64, 3-stage cp.async pipeline, 80B-padded smem rows.

#define M_DIM 2048
#define N_DIM 4096
#define K_DIM 4096

__device__ int8_t g_q1[(size_t)M_DIM * K_DIM];
__device__ int8_t g_q2[(size_t)M_DIM * K_DIM];
__device__ int8_t g_wq[(size_t)N_DIM * K_DIM];
__device__ float  g_step[M_DIM * 2];

// ---------------- helpers ----------------
__device__ __forceinline__ uint32_t smem_u32(const void* p) {
    uint32_t a;
    asm("{ .reg .u64 t; cvta.to.shared.u64 t, %1; cvt.u32.u64 %0, t; }" : "=r"(a) : "l"(p));
    return a;
}
__device__ __forceinline__ void cp_async16(uint32_t dst, const void* src) {
    asm volatile("cp.async.cg.shared.global [%0], [%1], 16;" :: "r"(dst), "l"(src));
}
__device__ __forceinline__ void cp_commit() {
    asm volatile("cp.async.commit_group;" ::: "memory");
}
template <int N_>
__device__ __forceinline__ void cp_wait() {
    asm volatile("cp.async.wait_group %0;" :: "n"(N_) : "memory");
}
__device__ __forceinline__ uint32_t lds32(uint32_t addr) {
    uint32_t v;
    asm volatile("ld.shared.b32 %0, [%1];" : "=r"(v) : "r"(addr));
    return v;
}
__device__ __forceinline__ void imma16832(int* d, const uint32_t* a, const uint32_t* b) {
    asm volatile(
        "mma.sync.aligned.m16n8k32.row.col.s32.s8.s8.s32 "
        "{%0,%1,%2,%3}, {%4,%5,%6,%7}, {%8,%9}, {%0,%1,%2,%3};"
        : "+r"(d[0]), "+r"(d[1]), "+r"(d[2]), "+r"(d[3])
        : "r"(a[0]), "r"(a[1]), "r"(a[2]), "r"(a[3]), "r"(b[0]), "r"(b[1]));
}

// ---------------- prep: per-row double quantization of x ----------------
__global__ __launch_bounds__(256)
void quant_x_kernel(const float* __restrict__ x) {
    const int m = blockIdx.x;
    const int tid = threadIdx.x;
    const float4* row4 = reinterpret_cast<const float4*>(x + (size_t)m * K_DIM);

    float amax = 0.f;
    for (int i = tid; i < K_DIM / 4; i += 256) {
        float4 v = row4[i];
        amax = fmaxf(amax, fmaxf(fmaxf(fabsf(v.x), fabsf(v.y)),
                                 fmaxf(fabsf(v.z), fabsf(v.w))));
    }
    #pragma unroll
    for (int o = 16; o > 0; o >>= 1)
        amax = fmaxf(amax, __shfl_xor_sync(0xFFFFFFFFu, amax, o));
    __shared__ float wmax[8];
    if ((tid & 31) == 0) wmax[tid >> 5] = amax;
    __syncthreads();
    float bmax = wmax[0];
    #pragma unroll
    for (int w = 1; w < 8; w++) bmax = fmaxf(bmax, wmax[w]);

    const float step1 = fmaxf(bmax * (1.0f / 127.0f), 1e-30f);
    const float step2 = step1 * (1.0f / 256.0f);
    const float inv1 = 1.0f / step1;
    const float inv2 = 1.0f / step2;

    uint32_t* q1o = reinterpret_cast<uint32_t*>(g_q1 + (size_t)m * K_DIM);
    uint32_t* q2o = reinterpret_cast<uint32_t*>(g_q2 + (size_t)m * K_DIM);
    for (int i = tid; i < K_DIM / 4; i += 256) {
        float4 v = row4[i];
        uint32_t p1 = 0, p2 = 0;
        float vv[4] = {v.x, v.y, v.z, v.w};
        #pragma unroll
        for (int j = 0; j < 4; j++) {
            int q1 = __float2int_rn(vv[j] * inv1);
            q1 = max(-127, min(127, q1));
            float r = fmaf((float)(-q1), step1, vv[j]);
            int q2 = __float2int_rn(r * inv2);
            q2 = max(-127, min(127, q2));
            p1 |= ((uint32_t)q1 & 0xFFu) << (8 * j);
            p2 |= ((uint32_t)q2 & 0xFFu) << (8 * j);
        }
        q1o[i] = p1;
        q2o[i] = p2;
    }
    if (tid == 0) {
        g_step[2 * m + 0] = step1;
        g_step[2 * m + 1] = step2;
    }
}

// ---------------- prep: pack int32 weights -> int8 ----------------
__global__ __launch_bounds__(256)
void pack_w_kernel(const int4* __restrict__ w, int n4) {
    int i = blockIdx.x * blockDim.x + threadIdx.x;
    if (i >= n4) return;
    int4 q = w[i];
    uint32_t p = ((uint32_t)q.x & 0xFFu) | (((uint32_t)q.y & 0xFFu) << 8) |
                 (((uint32_t)q.z & 0xFFu) << 16) | (((uint32_t)q.w & 0xFFu) << 24);
    reinterpret_cast<uint32_t*>(g_wq)[i] = p;
}

// ---------------- GEMM ----------------
#define BM 128
#define BN 128
#define BKB 64
#define ROW 80
#define TILE_B (128 * ROW)          // 10240
#define STAGE_B (3 * TILE_B)        // 30720: A1 | A2 | B
#define NSTAGES 3
#define SMEM_TOTAL (NSTAGES * STAGE_B)  // 92160

__global__ __launch_bounds__(256, 1)
void wint8_imma_kernel(const float* __restrict__ scales,
                       const float* __restrict__ bias,
                       float* __restrict__ out,
                       int M, int N, int K) {
    extern __shared__ __align__(128) char smem[];
    const uint32_t sb = smem_u32(smem);

    const int tid  = threadIdx.x;
    const int lane = tid & 31;
    const int wid  = tid >> 5;
    const int wm   = (wid >> 2) * 64;
    const int wn   = (wid & 3) * 32;
    const int fr   = lane >> 2;
    const int fc   = lane & 3;

    const int m0 = blockIdx.y * BM;
    const int n0 = blockIdx.x * BN;

    const int8_t* q1base = g_q1 + (size_t)m0 * K;
    const int8_t* q2base = g_q2 + (size_t)m0 * K;
    const int8_t* wqbase = g_wq + (size_t)n0 * K;

    auto load_stage = [&](int s, int kk) {
        const uint32_t st = sb + s * STAGE_B;
        #pragma unroll
        for (int p = 0; p < 2; p++) {
            const int chunk = tid + p * 256;    // 0..511
            const int r = chunk >> 2;
            const int c = chunk & 3;
            const uint32_t dst = st + r * ROW + c * 16;
            const size_t soff = (size_t)r * K + kk + c * 16;
            cp_async16(dst,              q1base + soff);
            cp_async16(dst + TILE_B,     q2base + soff);
            cp_async16(dst + 2 * TILE_B, wqbase + soff);
        }
    };

    const int NIT = K / BKB;   // 64

    load_stage(0, 0);
    cp_commit();
    load_stage(1, BKB);
    cp_commit();

    int acc1[4][4][4], acc2[4][4][4];
    #pragma unroll
    for (int mi = 0; mi < 4; mi++)
        #pragma unroll
        for (int ni = 0; ni < 4; ni++)
            #pragma unroll
            for (int c = 0; c < 4; c++) { acc1[mi][ni][c] = 0; acc2[mi][ni][c] = 0; }

    for (int it = 0; it < NIT; ++it) {
        cp_wait<NSTAGES - 2>();
        __syncthreads();

        const uint32_t st = sb + (it % NSTAGES) * STAGE_B;

        #pragma unroll
        for (int ks = 0; ks < 2; ks++) {
            const uint32_t koff = ks * 32 + fc * 4;

            uint32_t bfr[4][2];
            #pragma unroll
            for (int ni = 0; ni < 4; ni++) {
                const uint32_t ba = st + 2 * TILE_B + (wn + ni * 8 + fr) * ROW + koff;
                bfr[ni][0] = lds32(ba);
                bfr[ni][1] = lds32(ba + 16);
            }
            #pragma unroll
            for (int mi = 0; mi < 4; mi++) {
                const uint32_t aa = st + (wm + mi * 16 + fr) * ROW + koff;
                uint32_t a[4];
                a[0] = lds32(aa);
                a[1] = lds32(aa + 8 * ROW);
                a[2] = lds32(aa + 16);
                a[3] = lds32(aa + 8 * ROW + 16);
                #pragma unroll
                for (int ni = 0; ni < 4; ni++) imma16832(acc1[mi][ni], a, bfr[ni]);
            }
            #pragma unroll
            for (int mi = 0; mi < 4; mi++) {
                const uint32_t aa = st + TILE_B + (wm + mi * 16 + fr) * ROW + koff;
                uint32_t a[4];
                a[0] = lds32(aa);
                a[1] = lds32(aa + 8 * ROW);
                a[2] = lds32(aa + 16);
                a[3] = lds32(aa + 8 * ROW + 16);
                #pragma unroll
                for (int ni = 0; ni < 4; ni++) imma16832(acc2[mi][ni], a, bfr[ni]);
            }
        }

        __syncthreads();
        const int nxt = it + NSTAGES - 1;
        if (nxt < NIT) load_stage(nxt % NSTAGES, nxt * BKB);
        cp_commit();
    }

    // ---- epilogue: y = (step1*S1 + step2*S2) * scale + bias ----
    #pragma unroll
    for (int ni = 0; ni < 4; ni++) {
        const int col = n0 + wn + ni * 8 + fc * 2;
        const float sc0 = __ldg(&scales[col]);
        const float sc1 = __ldg(&scales[col + 1]);
        const float bi0 = __ldg(&bias[col]);
        const float bi1 = __ldg(&bias[col + 1]);
        #pragma unroll
        for (int mi = 0; mi < 4; mi++) {
            const int r0 = m0 + wm + mi * 16 + fr;
            const float s1a = g_step[2 * r0 + 0],       s2a = g_step[2 * r0 + 1];
            const float s1b = g_step[2 * (r0 + 8) + 0], s2b = g_step[2 * (r0 + 8) + 1];
            float2 oa, ob;
            oa.x = fmaf(fmaf(s1a, (float)acc1[mi][ni][0], s2a * (float)acc2[mi][ni][0]), sc0, bi0);
            oa.y = fmaf(fmaf(s1a, (float)acc1[mi][ni][1], s2a * (float)acc2[mi][ni][1]), sc1, bi1);
            ob.x = fmaf(fmaf(s1b, (float)acc1[mi][ni][2], s2b * (float)acc2[mi][ni][2]), sc0, bi0);
            ob.y = fmaf(fmaf(s1b, (float)acc1[mi][ni][3], s2b * (float)acc2[mi][ni][3]), sc1, bi1);
            *reinterpret_cast<float2*>(out + (size_t)r0 * N + col) = oa;
            *reinterpret_cast<float2*>(out + (size_t)(r0 + 8) * N + col) = ob;
        }
    }
}

extern "C" void kernel_launch(void* const* d_in, const int* in_sizes, int n_in,
                              void* d_out, int out_size) {
    const float* x      = (const float*)d_in[0];
    const int*   weight = (const int*)d_in[1];     // int32 (harness-widened int8)
    const float* scales = (const float*)d_in[2];
    const float* bias   = (const float*)d_in[3];
    float*       out    = (float*)d_out;

    const int N = in_sizes[2];            // 4096
    const int K = in_sizes[1] / N;        // 4096
    const int M = in_sizes[0] / K;        // 2048

    quant_x_kernel<<<M, 256>>>(x);
    const int wn4 = N * K / 4;
    pack_w_kernel<<<(wn4 + 255) / 256, 256>>>((const int4*)weight, wn4);

    cudaFuncSetAttribute(wint8_imma_kernel,
                         cudaFuncAttributeMaxDynamicSharedMemorySize, SMEM_TOTAL);
    dim3 grid(N / BN, M / BM);   // (32, 16)
    wint8_imma_kernel<<<grid, 256, SMEM_TOTAL>>>(scales, bias, out, M, N, K);
}

// round 12
// speedup vs baseline: 4.7653x; 4.7653x over previous
#include <cuda_runtime.h>
#include <cuda_fp16.h>
#include <cstdint>

// WeightOnlyInt8Linear on GB300 — fp16 HMMA (mma.sync.m16n8k16) single pass.
// out[M,N] = x[M,K] @ W[N,K]^T * scales[N] + bias[N],  M=2048, N=4096, K=4096.
//
// s8 mma.sync measured ~10x slow on sm_103a (no legacy IMMA pipe); fp16 has the
// same 11-bit significand as tf32 (measured rel_err 2.08e-4) at 2x MACs/instr.
// ldmatrix.x4 feeding cuts issue slots ~3x vs scalar LDS. W int8-valued -> exact fp16.

#define M_DIM 2048
#define N_DIM 4096
#define K_DIM 4096

__device__ __half g_xh[(size_t)M_DIM * K_DIM];   // 16 MB
__device__ __half g_wh[(size_t)N_DIM * K_DIM];   // 32 MB

// ---------------- helpers ----------------
__device__ __forceinline__ uint32_t smem_u32(const void* p) {
    uint32_t a;
    asm("{ .reg .u64 t; cvta.to.shared.u64 t, %1; cvt.u32.u64 %0, t; }" : "=r"(a) : "l"(p));
    return a;
}
__device__ __forceinline__ uint32_t h2_bits(__half2 h) {
    return *reinterpret_cast<uint32_t*>(&h);
}
__device__ __forceinline__ void cp_async16(uint32_t dst, const void* src) {
    asm volatile("cp.async.cg.shared.global [%0], [%1], 16;" :: "r"(dst), "l"(src));
}
__device__ __forceinline__ void cp_commit() {
    asm volatile("cp.async.commit_group;" ::: "memory");
}
template <int N_>
__device__ __forceinline__ void cp_wait() {
    asm volatile("cp.async.wait_group %0;" :: "n"(N_) : "memory");
}
__device__ __forceinline__ void ldmatrix_x4(uint32_t* r, uint32_t addr) {
    asm volatile("ldmatrix.sync.aligned.m8n8.x4.shared.b16 {%0,%1,%2,%3}, [%4];"
                 : "=r"(r[0]), "=r"(r[1]), "=r"(r[2]), "=r"(r[3]) : "r"(addr));
}
__device__ __forceinline__ void mma_f16(float* d, const uint32_t* a, const uint32_t* b) {
    asm volatile(
        "mma.sync.aligned.m16n8k16.row.col.f32.f16.f16.f32 "
        "{%0,%1,%2,%3}, {%4,%5,%6,%7}, {%8,%9}, {%0,%1,%2,%3};"
        : "+f"(d[0]), "+f"(d[1]), "+f"(d[2]), "+f"(d[3])
        : "r"(a[0]), "r"(a[1]), "r"(a[2]), "r"(a[3]), "r"(b[0]), "r"(b[1]));
}

// ---------------- prep: x fp32 -> fp16, W int32 -> fp16 (exact) ----------------
__global__ __launch_bounds__(256)
void convert_xh_kernel(const float4* __restrict__ x, int n8) {
    int i = blockIdx.x * blockDim.x + threadIdx.x;
    if (i >= n8) return;
    float4 v0 = x[2 * i];
    float4 v1 = x[2 * i + 1];
    uint4 o;
    o.x = h2_bits(__floats2half2_rn(v0.x, v0.y));
    o.y = h2_bits(__floats2half2_rn(v0.z, v0.w));
    o.z = h2_bits(__floats2half2_rn(v1.x, v1.y));
    o.w = h2_bits(__floats2half2_rn(v1.z, v1.w));
    reinterpret_cast<uint4*>(g_xh)[i] = o;
}
__global__ __launch_bounds__(256)
void convert_wh_kernel(const int4* __restrict__ w, int n8) {
    int i = blockIdx.x * blockDim.x + threadIdx.x;
    if (i >= n8) return;
    int4 q0 = w[2 * i];
    int4 q1 = w[2 * i + 1];
    uint4 o;
    o.x = h2_bits(__floats2half2_rn((float)q0.x, (float)q0.y));
    o.y = h2_bits(__floats2half2_rn((float)q0.z, (float)q0.w));
    o.z = h2_bits(__floats2half2_rn((float)q1.x, (float)q1.y));
    o.w = h2_bits(__floats2half2_rn((float)q1.z, (float)q1.w));
    reinterpret_cast<uint4*>(g_wh)[i] = o;
}

// ---------------- GEMM ----------------
#define BM 128
#define BN 128
#define BKH 64                     // k elements per stage (fp16)
#define ROW 144                    // 128B data + 16B pad per smem row
#define TILE_B (128 * ROW)         // 18432
#define STAGE_B (2 * TILE_B)       // 36864 (A | B)
#define NSTAGES 3
#define SMEM_TOTAL (NSTAGES * STAGE_B)  // 110592

__global__ __launch_bounds__(256, 2)
void wint8_hmma_kernel(const float* __restrict__ scales,
                       const float* __restrict__ bias,
                       float* __restrict__ out,
                       int M, int N, int K) {
    extern __shared__ __align__(128) char smem[];
    const uint32_t sb = smem_u32(smem);

    const int tid  = threadIdx.x;
    const int lane = tid & 31;
    const int wid  = tid >> 5;
    const int wm   = (wid >> 2) * 64;   // warp M offset (2 warps in M)
    const int wn   = (wid & 3) * 32;    // warp N offset (4 warps in N)
    const int fr   = lane >> 2;
    const int fc   = lane & 3;

    const int m0 = blockIdx.y * BM;
    const int n0 = blockIdx.x * BN;

    const __half* xbase = g_xh + (size_t)m0 * K;
    const __half* wbase = g_wh + (size_t)n0 * K;

    // cp.async: per tile 128 rows x 8 x 16B = 1024 chunks; 2 tiles, 256 thr -> 8 each
    auto load_stage = [&](int s, int kk) {
        const uint32_t st = sb + s * STAGE_B;
        #pragma unroll
        for (int p = 0; p < 4; p++) {
            const int chunk = tid + p * 256;       // 0..1023
            const int r = chunk >> 3;
            const int c = chunk & 7;
            const uint32_t dst = st + r * ROW + c * 16;
            const size_t soff = (size_t)r * K + kk + c * 8;
            cp_async16(dst,          xbase + soff);
            cp_async16(dst + TILE_B, wbase + soff);
        }
    };

    const int NIT = K / BKH;   // 64

    load_stage(0, 0);
    cp_commit();
    load_stage(1, BKH);
    cp_commit();

    float acc[4][4][4];
    #pragma unroll
    for (int mi = 0; mi < 4; mi++)
        #pragma unroll
        for (int ni = 0; ni < 4; ni++)
            #pragma unroll
            for (int c = 0; c < 4; c++) acc[mi][ni][c] = 0.0f;

    // ldmatrix per-lane address components
    const int a_r  = lane & 15;            // row within 16-row frag
    const int a_c  = (lane >> 4) * 16;     // 0 or 16 bytes (k +8 elems)
    const int b_t  = lane >> 3;            // tile 0..3
    const int b_r  = ((b_t & 2) << 2) + (lane & 7);  // 0..15 row within 16-n pair
    const int b_c  = (b_t & 1) * 16;       // 0 or 16 bytes

    for (int it = 0; it < NIT; ++it) {
        cp_wait<NSTAGES - 2>();
        __syncthreads();

        const uint32_t st = sb + (it % NSTAGES) * STAGE_B;
        const uint32_t abase = st + (wm + a_r) * ROW + a_c;
        const uint32_t bbase = st + TILE_B + (wn + b_r) * ROW + b_c;

        #pragma unroll
        for (int ks = 0; ks < 4; ks++) {
            const uint32_t ko = ks * 32;   // 16 halfs = 32B
            uint32_t af[4][4];
            #pragma unroll
            for (int mi = 0; mi < 4; mi++)
                ldmatrix_x4(af[mi], abase + mi * (16 * ROW) + ko);
            uint32_t bf[2][4];
            #pragma unroll
            for (int p = 0; p < 2; p++)
                ldmatrix_x4(bf[p], bbase + p * (16 * ROW) + ko);
            #pragma unroll
            for (int mi = 0; mi < 4; mi++)
                #pragma unroll
                for (int ni = 0; ni < 4; ni++)
                    mma_f16(acc[mi][ni], af[mi], &bf[ni >> 1][(ni & 1) * 2]);
        }

        __syncthreads();
        const int nxt = it + NSTAGES - 1;
        if (nxt < NIT) load_stage(nxt % NSTAGES, nxt * BKH);
        cp_commit();
    }

    // ---- epilogue: scale + bias, float2 stores ----
    #pragma unroll
    for (int ni = 0; ni < 4; ni++) {
        const int col = n0 + wn + ni * 8 + fc * 2;
        const float s0 = __ldg(&scales[col]);
        const float s1 = __ldg(&scales[col + 1]);
        const float g0 = __ldg(&bias[col]);
        const float g1 = __ldg(&bias[col + 1]);
        #pragma unroll
        for (int mi = 0; mi < 4; mi++) {
            const int row = m0 + wm + mi * 16 + fr;
            float2 o0, o1;
            o0.x = fmaf(acc[mi][ni][0], s0, g0);
            o0.y = fmaf(acc[mi][ni][1], s1, g1);
            o1.x = fmaf(acc[mi][ni][2], s0, g0);
            o1.y = fmaf(acc[mi][ni][3], s1, g1);
            *reinterpret_cast<float2*>(out + (size_t)row * N + col) = o0;
            *reinterpret_cast<float2*>(out + (size_t)(row + 8) * N + col) = o1;
        }
    }
}

extern "C" void kernel_launch(void* const* d_in, const int* in_sizes, int n_in,
                              void* d_out, int out_size) {
    const float* x      = (const float*)d_in[0];
    const int*   weight = (const int*)d_in[1];     // int32 (harness-widened int8)
    const float* scales = (const float*)d_in[2];
    const float* bias   = (const float*)d_in[3];
    float*       out    = (float*)d_out;

    const int N = in_sizes[2];            // 4096
    const int K = in_sizes[1] / N;        // 4096
    const int M = in_sizes[0] / K;        // 2048

    const int xn8 = M * K / 8;
    const int wn8 = N * K / 8;
    convert_xh_kernel<<<(xn8 + 255) / 256, 256>>>((const float4*)x, xn8);
    convert_wh_kernel<<<(wn8 + 255) / 256, 256>>>((const int4*)weight, wn8);

    cudaFuncSetAttribute(wint8_hmma_kernel,
                         cudaFuncAttributeMaxDynamicSharedMemorySize, SMEM_TOTAL);
    dim3 grid(N / BN, M / BM);   // (32, 16)
    wint8_hmma_kernel<<<grid, 256, SMEM_TOTAL>>>(scales, bias, out, M, N, K);
}

// round 14
// speedup vs baseline: 5.0215x; 1.0538x over previous
#include <cuda_runtime.h>
#include <cuda_fp16.h>
#include <cstdint>

// WeightOnlyInt8Linear on GB300 — fp16 HMMA (mma.sync.m16n8k16) single pass.
// out[M,N] = x[M,K] @ W[N,K]^T * scales[N] + bias[N],  M=2048, N=4096, K=4096.
//
// R12: 246.5us, rel_err 2.075e-4, GEMM ~210us (~54% fp16-tensor util).
// R13/14: single barrier per mainloop iteration; next-stage cp.async issued
// immediately after the barrier (before compute) — safe because passing the
// barrier at iter `it` implies all warps finished reading stage (it+2)%3
// during iter it-1. Removes 64 BARs/CTA and deepens prefetch.

#define M_DIM 2048
#define N_DIM 4096
#define K_DIM 4096

__device__ __half g_xh[(size_t)M_DIM * K_DIM];   // 16 MB
__device__ __half g_wh[(size_t)N_DIM * K_DIM];   // 32 MB

// ---------------- helpers ----------------
__device__ __forceinline__ uint32_t smem_u32(const void* p) {
    uint32_t a;
    asm("{ .reg .u64 t; cvta.to.shared.u64 t, %1; cvt.u32.u64 %0, t; }" : "=r"(a) : "l"(p));
    return a;
}
__device__ __forceinline__ uint32_t h2_bits(__half2 h) {
    return *reinterpret_cast<uint32_t*>(&h);
}
__device__ __forceinline__ void cp_async16(uint32_t dst, const void* src) {
    asm volatile("cp.async.cg.shared.global [%0], [%1], 16;" :: "r"(dst), "l"(src));
}
__device__ __forceinline__ void cp_commit() {
    asm volatile("cp.async.commit_group;" ::: "memory");
}
template <int N_>
__device__ __forceinline__ void cp_wait() {
    asm volatile("cp.async.wait_group %0;" :: "n"(N_) : "memory");
}
__device__ __forceinline__ void ldmatrix_x4(uint32_t* r, uint32_t addr) {
    asm volatile("ldmatrix.sync.aligned.m8n8.x4.shared.b16 {%0,%1,%2,%3}, [%4];"
                 : "=r"(r[0]), "=r"(r[1]), "=r"(r[2]), "=r"(r[3]) : "r"(addr));
}
__device__ __forceinline__ void mma_f16(float* d, const uint32_t* a, const uint32_t* b) {
    asm volatile(
        "mma.sync.aligned.m16n8k16.row.col.f32.f16.f16.f32 "
        "{%0,%1,%2,%3}, {%4,%5,%6,%7}, {%8,%9}, {%0,%1,%2,%3};"
        : "+f"(d[0]), "+f"(d[1]), "+f"(d[2]), "+f"(d[3])
        : "r"(a[0]), "r"(a[1]), "r"(a[2]), "r"(a[3]), "r"(b[0]), "r"(b[1]));
}

// ---------------- prep: x fp32 -> fp16, W int32 -> fp16 (exact) ----------------
__global__ __launch_bounds__(256)
void convert_xh_kernel(const float4* __restrict__ x, int n8) {
    int i = blockIdx.x * blockDim.x + threadIdx.x;
    if (i >= n8) return;
    float4 v0 = x[2 * i];
    float4 v1 = x[2 * i + 1];
    uint4 o;
    o.x = h2_bits(__floats2half2_rn(v0.x, v0.y));
    o.y = h2_bits(__floats2half2_rn(v0.z, v0.w));
    o.z = h2_bits(__floats2half2_rn(v1.x, v1.y));
    o.w = h2_bits(__floats2half2_rn(v1.z, v1.w));
    reinterpret_cast<uint4*>(g_xh)[i] = o;
}
__global__ __launch_bounds__(256)
void convert_wh_kernel(const int4* __restrict__ w, int n8) {
    int i = blockIdx.x * blockDim.x + threadIdx.x;
    if (i >= n8) return;
    int4 q0 = w[2 * i];
    int4 q1 = w[2 * i + 1];
    uint4 o;
    o.x = h2_bits(__floats2half2_rn((float)q0.x, (float)q0.y));
    o.y = h2_bits(__floats2half2_rn((float)q0.z, (float)q0.w));
    o.z = h2_bits(__floats2half2_rn((float)q1.x, (float)q1.y));
    o.w = h2_bits(__floats2half2_rn((float)q1.z, (float)q1.w));
    reinterpret_cast<uint4*>(g_wh)[i] = o;
}

// ---------------- GEMM ----------------
#define BM 128
#define BN 128
#define BKH 64                     // k elements per stage (fp16)
#define ROW 144                    // 128B data + 16B pad per smem row
#define TILE_B (128 * ROW)         // 18432
#define STAGE_B (2 * TILE_B)       // 36864 (A | B)
#define NSTAGES 3
#define SMEM_TOTAL (NSTAGES * STAGE_B)  // 110592

__global__ __launch_bounds__(256, 2)
void wint8_hmma_kernel(const float* __restrict__ scales,
                       const float* __restrict__ bias,
                       float* __restrict__ out,
                       int M, int N, int K) {
    extern __shared__ __align__(128) char smem[];
    const uint32_t sb = smem_u32(smem);

    const int tid  = threadIdx.x;
    const int lane = tid & 31;
    const int wid  = tid >> 5;
    const int wm   = (wid >> 2) * 64;   // warp M offset (2 warps in M)
    const int wn   = (wid & 3) * 32;    // warp N offset (4 warps in N)
    const int fr   = lane >> 2;
    const int fc   = lane & 3;

    const int m0 = blockIdx.y * BM;
    const int n0 = blockIdx.x * BN;

    const __half* xbase = g_xh + (size_t)m0 * K;
    const __half* wbase = g_wh + (size_t)n0 * K;

    // cp.async: per tile 128 rows x 8 x 16B = 1024 chunks; 2 tiles, 256 thr -> 8 each
    auto load_stage = [&](int s, int kk) {
        const uint32_t st = sb + s * STAGE_B;
        #pragma unroll
        for (int p = 0; p < 4; p++) {
            const int chunk = tid + p * 256;       // 0..1023
            const int r = chunk >> 3;
            const int c = chunk & 7;
            const uint32_t dst = st + r * ROW + c * 16;
            const size_t soff = (size_t)r * K + kk + c * 8;
            cp_async16(dst,          xbase + soff);
            cp_async16(dst + TILE_B, wbase + soff);
        }
    };

    const int NIT = K / BKH;   // 64

    load_stage(0, 0);
    cp_commit();
    load_stage(1, BKH);
    cp_commit();

    float acc[4][4][4];
    #pragma unroll
    for (int mi = 0; mi < 4; mi++)
        #pragma unroll
        for (int ni = 0; ni < 4; ni++)
            #pragma unroll
            for (int c = 0; c < 4; c++) acc[mi][ni][c] = 0.0f;

    // ldmatrix per-lane address components
    const int a_r  = lane & 15;            // row within 16-row frag
    const int a_c  = (lane >> 4) * 16;     // 0 or 16 bytes (k +8 elems)
    const int b_t  = lane >> 3;            // tile 0..3
    const int b_r  = ((b_t & 2) << 2) + (lane & 7);  // 0..15 row within 16-n pair
    const int b_c  = (b_t & 1) * 16;       // 0 or 16 bytes

    for (int it = 0; it < NIT; ++it) {
        cp_wait<NSTAGES - 2>();
        __syncthreads();

        // Issue next-stage loads BEFORE compute: stage (it+2)%3 was last read
        // during iter it-1; every warp past this barrier has finished that read.
        const int nxt = it + NSTAGES - 1;
        if (nxt < NIT) load_stage(nxt % NSTAGES, nxt * BKH);
        cp_commit();

        const uint32_t st = sb + (it % NSTAGES) * STAGE_B;
        const uint32_t abase = st + (wm + a_r) * ROW + a_c;
        const uint32_t bbase = st + TILE_B + (wn + b_r) * ROW + b_c;

        #pragma unroll
        for (int ks = 0; ks < 4; ks++) {
            const uint32_t ko = ks * 32;   // 16 halfs = 32B
            uint32_t af[4][4];
            #pragma unroll
            for (int mi = 0; mi < 4; mi++)
                ldmatrix_x4(af[mi], abase + mi * (16 * ROW) + ko);
            uint32_t bf[2][4];
            #pragma unroll
            for (int p = 0; p < 2; p++)
                ldmatrix_x4(bf[p], bbase + p * (16 * ROW) + ko);
            #pragma unroll
            for (int mi = 0; mi < 4; mi++)
                #pragma unroll
                for (int ni = 0; ni < 4; ni++)
                    mma_f16(acc[mi][ni], af[mi], &bf[ni >> 1][(ni & 1) * 2]);
        }
    }

    // ---- epilogue: scale + bias, float2 stores ----
    #pragma unroll
    for (int ni = 0; ni < 4; ni++) {
        const int col = n0 + wn + ni * 8 + fc * 2;
        const float s0 = __ldg(&scales[col]);
        const float s1 = __ldg(&scales[col + 1]);
        const float g0 = __ldg(&bias[col]);
        const float g1 = __ldg(&bias[col + 1]);
        #pragma unroll
        for (int mi = 0; mi < 4; mi++) {
            const int row = m0 + wm + mi * 16 + fr;
            float2 o0, o1;
            o0.x = fmaf(acc[mi][ni][0], s0, g0);
            o0.y = fmaf(acc[mi][ni][1], s1, g1);
            o1.x = fmaf(acc[mi][ni][2], s0, g0);
            o1.y = fmaf(acc[mi][ni][3], s1, g1);
            *reinterpret_cast<float2*>(out + (size_t)row * N + col) = o0;
            *reinterpret_cast<float2*>(out + (size_t)(row + 8) * N + col) = o1;
        }
    }
}

extern "C" void kernel_launch(void* const* d_in, const int* in_sizes, int n_in,
                              void* d_out, int out_size) {
    const float* x      = (const float*)d_in[0];
    const int*   weight = (const int*)d_in[1];     // int32 (harness-widened int8)
    const float* scales = (const float*)d_in[2];
    const float* bias   = (const float*)d_in[3];
    float*       out    = (float*)d_out;

    const int N = in_sizes[2];            // 4096
    const int K = in_sizes[1] / N;        // 4096
    const int M = in_sizes[0] / K;        // 2048

    const int xn8 = M * K / 8;
    const int wn8 = N * K / 8;
    convert_xh_kernel<<<(xn8 + 255) / 256, 256>>>((const float4*)x, xn8);
    convert_wh_kernel<<<(wn8 + 255) / 256, 256>>>((const int4*)weight, wn8);

    cudaFuncSetAttribute(wint8_hmma_kernel,
                         cudaFuncAttributeMaxDynamicSharedMemorySize, SMEM_TOTAL);
    dim3 grid(N / BN, M / BM);   // (32, 16)
    wint8_hmma_kernel<<<grid, 256, SMEM_TOTAL>>>(scales, bias, out, M, N, K);
}